// round 15
// baseline (speedup 1.0000x reference)
#include <cuda_runtime.h>

#define NB 8
#define NV 256
#define ND 64
#define NH 128
#define NI 32
#define NT 50
#define ROWS 16
#define XS 20
#define NTHR 256
#define GRID 128
#define CLUSTER 16

#define WORK0 0
#define WORK1 4096
#define W_IN  8192
#define W_H0  16384
#define W_H1  32768
#define W_OUT 49152
#define SM_FLOATS 57344
#define G_WR  16384
#define G_WZ  (16384 + 6144)
#define G_WG  (16384 + 12288)
#define G_WO  (16384 + 18432)

typedef unsigned long long ull;
union F4U { float4 f; ull u[2]; };
union U2F { ull u; float2 f; };
#define FMA2(acc, x, w) asm("fma.rn.f32x2 %0, %1, %2, %0;" : "+l"(acc) : "l"(x), "l"(w))
#define PACK2(d, s)     asm("mov.b64 %0, {%1, %1};" : "=l"(d) : "f"(s))

__device__ __forceinline__ float fast_tanh(float x) {
    float e = __expf(-2.0f * fabsf(x));
    float t = __fdividef(1.0f - e, 1.0f + e);
    return copysignf(t, x);
}
__device__ __forceinline__ float fast_sig(float x) {
    return __fdividef(1.0f, 1.0f + __expf(-x));
}
__device__ __forceinline__ void cluster_barrier() {
    __syncthreads();
    __threadfence();
    asm volatile("barrier.cluster.arrive.aligned;" ::: "memory");
    asm volatile("barrier.cluster.wait.aligned;" ::: "memory");
}
__device__ __forceinline__ void smcopy(float* dst, const float* src, int nfloats, int t) {
    float4* d4 = (float4*)dst;
    const float4* s4 = (const float4*)src;
    int n4 = nfloats >> 2;
    for (int i = t; i < n4; i += NTHR) d4[i] = s4[i];
}

// hidden layer Kout=128: 16r x 128c, 256 thr, tile 4r x 2c, r-paired FFMA2.
// xin/xout [k][r] stride XS (row pairs contiguous -> direct u64 operands).
template <int KIN>
__device__ __forceinline__ void layer128(int t, const float* W,
                                         const float* __restrict__ bias,
                                         const float* xin, float* xout) {
    const int c2 = (t & 63) * 2;
    const int r4 = (t >> 6) * 4;
    ull a0 = 0ULL, a1 = 0ULL, a2 = 0ULL, a3 = 0ULL; // (c0,r01)(c0,r23)(c1,r01)(c1,r23)
    const float* xp = xin + r4;
    const float* wp = W + c2;
#pragma unroll 8
    for (int k = 0; k < KIN; k++) {
        F4U xv; xv.f = *(const float4*)xp;
        float2 wv = *(const float2*)wp;
        xp += XS; wp += NH;
        ull w0, w1;
        PACK2(w0, wv.x); PACK2(w1, wv.y);
        FMA2(a0, xv.u[0], w0); FMA2(a1, xv.u[1], w0);
        FMA2(a2, xv.u[0], w1); FMA2(a3, xv.u[1], w1);
    }
    float b0 = __ldg(bias + c2), b1 = __ldg(bias + c2 + 1);
    U2F s0, s1;
    s0.u = a0; s1.u = a1;
    xout[c2 * XS + r4 + 0] = fast_tanh(s0.f.x + b0);
    xout[c2 * XS + r4 + 1] = fast_tanh(s0.f.y + b0);
    xout[c2 * XS + r4 + 2] = fast_tanh(s1.f.x + b0);
    xout[c2 * XS + r4 + 3] = fast_tanh(s1.f.y + b0);
    s0.u = a2; s1.u = a3;
    xout[(c2 + 1) * XS + r4 + 0] = fast_tanh(s0.f.x + b1);
    xout[(c2 + 1) * XS + r4 + 1] = fast_tanh(s0.f.y + b1);
    xout[(c2 + 1) * XS + r4 + 2] = fast_tanh(s1.f.x + b1);
    xout[(c2 + 1) * XS + r4 + 3] = fast_tanh(s1.f.y + b1);
}

// agg = adj @ h -> WORK0 [d][r] stride XS. h streamed in 8x32-row chunks,
// double-buffered in WORK1. d-paired FFMA2 (h float4 = two u64 pairs).
__device__ __forceinline__ void stage_agg(float* sm, int t, const float* __restrict__ adjb,
                                          const float* __restrict__ hb, int bcast) {
    const int d4 = (t & 15) * 4;
    const int rg = ((t >> 4) & 3) * 4;
    const int wq = t >> 6;  // 0..3
    ull acc[8];
#pragma unroll
    for (int i = 0; i < 8; i++) acc[i] = 0ULL;

    if (bcast) {
        F4U h4; h4.f = *(const float4*)(hb + d4);
#pragma unroll
        for (int i = 0; i < 4; i++) {
            int idx = t + i * NTHR;
            *(float4*)(sm + idx * 4) = *(const float4*)(adjb + idx * 4);
        }
        __syncthreads();
#pragma unroll 4
        for (int w = 0; w < 64; w++) {
            int wa = wq * 64 + w;
#pragma unroll
            for (int rr = 0; rr < 4; rr++) {
                ull ap; PACK2(ap, sm[(rg + rr) * NV + wa]);
                FMA2(acc[2 * rr], ap, h4.u[0]);
                FMA2(acc[2 * rr + 1], ap, h4.u[1]);
            }
        }
        __syncthreads();
    } else {
        float* hbuf = sm + WORK1;  // 2 x 2048 floats
        float4 p0 = *(const float4*)(hb + t * 8);
        float4 p1 = *(const float4*)(hb + t * 8 + 4);
#pragma unroll
        for (int i = 0; i < 4; i++) {
            int idx = t + i * NTHR;
            *(float4*)(sm + idx * 4) = *(const float4*)(adjb + idx * 4);
        }
        *(float4*)(hbuf + t * 8) = p0;
        *(float4*)(hbuf + t * 8 + 4) = p1;
#pragma unroll 2
        for (int c = 0; c < 8; c++) {
            float4 q0, q1;
            if (c < 7) {
                const float* src = hb + (c + 1) * 2048 + t * 8;
                q0 = *(const float4*)src;
                q1 = *(const float4*)(src + 4);
            }
            __syncthreads();
            const float* hc = hbuf + (c & 1) * 2048;
#pragma unroll
            for (int w = 0; w < 8; w++) {
                int wl = wq * 8 + w;
                F4U h4; h4.f = *(const float4*)(hc + wl * 64 + d4);
                int wa = c * 32 + wl;
#pragma unroll
                for (int rr = 0; rr < 4; rr++) {
                    ull ap; PACK2(ap, sm[(rg + rr) * NV + wa]);
                    FMA2(acc[2 * rr], ap, h4.u[0]);
                    FMA2(acc[2 * rr + 1], ap, h4.u[1]);
                }
            }
            if (c < 7) {
                float* dst = hbuf + ((c + 1) & 1) * 2048 + t * 8;
                *(float4*)dst = q0;
                *(float4*)(dst + 4) = q1;
            }
        }
        __syncthreads();
    }

    float* pb = sm + WORK1;
#pragma unroll
    for (int rr = 0; rr < 4; rr++) {
        F4U o; o.u[0] = acc[2 * rr]; o.u[1] = acc[2 * rr + 1];
        *(float4*)(pb + wq * 1024 + (rg + rr) * ND + d4) = o.f;
    }
    __syncthreads();
#pragma unroll
    for (int i = 0; i < 4; i++) {
        int idx = t + i * NTHR;
        int r = idx >> 6, d = idx & 63;
        float s = pb[d + r * ND] + pb[1024 + d + r * ND] +
                  pb[2048 + d + r * ND] + pb[3072 + d + r * ND];
        sm[WORK0 + d * XS + r] = s;
    }
    __syncthreads();
}

__device__ void euler_step(float* sm, int t, const float* __restrict__ adjb,
                           const float* __restrict__ hb, int bcast, int v0,
                           const float* __restrict__ bin, const float* __restrict__ bh0,
                           const float* __restrict__ bh1, const float* __restrict__ bout,
                           float* __restrict__ out1, float* __restrict__ out2) {
    const int fc2 = (t & 31) * 2;
    const int fr2 = (t >> 5) * 2;
    float2 hpA, hpB;
    if (bcast) {
        hpA = *(const float2*)(hb + fc2);
        hpB = hpA;
    } else {
        hpA = *(const float2*)(hb + (v0 + fr2) * ND + fc2);
        hpB = *(const float2*)(hb + (v0 + fr2 + 1) * ND + fc2);
    }
    stage_agg(sm, t, adjb, hb, bcast);
    float* xA = sm + WORK0;
    float* xB = sm + WORK1;
    layer128<ND>(t, sm + W_IN, bin, xA, xB);
    __syncthreads();
    layer128<NH>(t, sm + W_H0, bh0, xB, xA);
    __syncthreads();
    layer128<NH>(t, sm + W_H1, bh1, xA, xB);
    __syncthreads();
    // final 128 -> 64: 2r x 2c, r-paired FFMA2
    {
        ull a0 = 0ULL, a1 = 0ULL;  // (c0, r01), (c1, r01)
        const float* xp = xB + fr2;
        const float* wp = sm + W_OUT + fc2;
#pragma unroll 8
        for (int k = 0; k < NH; k++) {
            ull xu = *(const ull*)xp;
            float2 wv = *(const float2*)wp;
            xp += XS; wp += ND;
            ull w0, w1;
            PACK2(w0, wv.x); PACK2(w1, wv.y);
            FMA2(a0, xu, w0); FMA2(a1, xu, w1);
        }
        float b0 = __ldg(bout + fc2), b1 = __ldg(bout + fc2 + 1);
        U2F sA, sB; sA.u = a0; sB.u = a1;
#pragma unroll
        for (int rr = 0; rr < 2; rr++) {
            float d0 = (rr == 0) ? sA.f.x : sA.f.y;
            float d1 = (rr == 0) ? sB.f.x : sB.f.y;
            float2 hp = (rr == 0) ? hpA : hpB;
            float2 o;
            o.x = hp.x + 0.25f * fast_tanh(d0 + b0);
            o.y = hp.y + 0.25f * fast_tanh(d1 + b1);
            *(float2*)(out1 + (v0 + fr2 + rr) * ND + fc2) = o;
            if (out2) *(float2*)(out2 + (v0 + fr2 + rr) * ND + fc2) = o;
        }
    }
}

// GRU correction (unchanged from the 6286us base).
__device__ void gru_step(float* sm, int t, const float* __restrict__ adjb,
                         const float* __restrict__ hb, int v0,
                         const float* __restrict__ vrow, const float* __restrict__ mrowg,
                         const float* __restrict__ br, const float* __restrict__ bz,
                         const float* __restrict__ bg, const float* __restrict__ bo,
                         float* __restrict__ post, float* __restrict__ xp) {
    float* aggT = sm + WORK0;
    float* h1T = sm + WORK0 + 64 * XS;
    float* xT = sm + WORK0 + 128 * XS;
    float* mrow = sm + WORK0 + 160 * XS;
    float* rT = sm + WORK1;
    float* zT = sm + WORK1 + 64 * XS;

    float h1pf[4];
#pragma unroll
    for (int i = 0; i < 4; i++) {
        int idx = t + i * NTHR;
        h1pf[i] = hb[(v0 + (idx >> 6)) * ND + (idx & 63)];
    }
    float vpf[2], mpf[2];
#pragma unroll
    for (int i = 0; i < 2; i++) {
        int idx = t + i * NTHR;
        int r = idx >> 5, c = idx & 31;
        vpf[i] = vrow[(v0 + r) * NI + c];
        mpf[i] = mrowg[(v0 + r) * NI + c];
    }
    stage_agg(sm, t, adjb, hb, 0);
#pragma unroll
    for (int i = 0; i < 4; i++) {
        int idx = t + i * NTHR;
        h1T[(idx & 63) * XS + (idx >> 6)] = h1pf[i];
    }
#pragma unroll
    for (int i = 0; i < 2; i++) {
        int idx = t + i * NTHR;
        int r = idx >> 5, c = idx & 31;
        xT[c * XS + r] = vpf[i] * mpf[i];
    }
    if (t < ROWS) {
        float s = 0.f;
        for (int c = 0; c < NI; c++) s += fabsf(mrowg[(v0 + t) * NI + c]);
        mrow[t] = (s > 1e-4f) ? 1.0f : 0.0f;
    }
    __syncthreads();

    const int c2 = (t & 31) * 2;
    const int r2 = (t >> 5) * 2;
    {
        float br0 = __ldg(br + c2), br1 = __ldg(br + c2 + 1);
        float bz0 = __ldg(bz + c2), bz1 = __ldg(bz + c2 + 1);
        float ar00 = 0.f, ar01 = 0.f, ar10 = 0.f, ar11 = 0.f;
        float az00 = 0.f, az01 = 0.f, az10 = 0.f, az11 = 0.f;
        const float* wr = sm + G_WR + c2;
        const float* wz = sm + G_WZ + c2;
        const float* xq = xT + r2;
#pragma unroll 4
        for (int k = 0; k < NI; k++) {
            float2 xv = *(const float2*)xq;
            float2 wrv = *(const float2*)wr;
            float2 wzv = *(const float2*)wz;
            xq += XS; wr += ND; wz += ND;
            ar00 += xv.x * wrv.x; ar01 += xv.x * wrv.y;
            ar10 += xv.y * wrv.x; ar11 += xv.y * wrv.y;
            az00 += xv.x * wzv.x; az01 += xv.x * wzv.y;
            az10 += xv.y * wzv.x; az11 += xv.y * wzv.y;
        }
        const float* xa = aggT + r2;
#pragma unroll 4
        for (int k = 0; k < ND; k++) {
            float2 xv = *(const float2*)xa;
            float2 wrv = *(const float2*)wr;
            float2 wzv = *(const float2*)wz;
            xa += XS; wr += ND; wz += ND;
            ar00 += xv.x * wrv.x; ar01 += xv.x * wrv.y;
            ar10 += xv.y * wrv.x; ar11 += xv.y * wrv.y;
            az00 += xv.x * wzv.x; az01 += xv.x * wzv.y;
            az10 += xv.y * wzv.x; az11 += xv.y * wzv.y;
        }
        rT[c2 * XS + r2 + 0] = fast_sig(ar00 + br0);
        rT[c2 * XS + r2 + 1] = fast_sig(ar10 + br0);
        rT[(c2 + 1) * XS + r2 + 0] = fast_sig(ar01 + br1);
        rT[(c2 + 1) * XS + r2 + 1] = fast_sig(ar11 + br1);
        zT[c2 * XS + r2 + 0] = fast_sig(az00 + bz0);
        zT[c2 * XS + r2 + 1] = fast_sig(az10 + bz0);
        zT[(c2 + 1) * XS + r2 + 0] = fast_sig(az01 + bz1);
        zT[(c2 + 1) * XS + r2 + 1] = fast_sig(az11 + bz1);
    }
    __syncthreads();
#pragma unroll
    for (int i = 0; i < 4; i++) {
        int idx = t + i * NTHR;
        int r = idx >> 6, d = idx & 63;
        rT[d * XS + r] *= aggT[d * XS + r];
    }
    __syncthreads();
    {
        float bg0 = __ldg(bg + c2), bg1 = __ldg(bg + c2 + 1);
        float ag00 = 0.f, ag01 = 0.f, ag10 = 0.f, ag11 = 0.f;
        const float* wg = sm + G_WG + c2;
        const float* xq = xT + r2;
#pragma unroll 4
        for (int k = 0; k < NI; k++) {
            float2 xv = *(const float2*)xq;
            float2 wgv = *(const float2*)wg;
            xq += XS; wg += ND;
            ag00 += xv.x * wgv.x; ag01 += xv.x * wgv.y;
            ag10 += xv.y * wgv.x; ag11 += xv.y * wgv.y;
        }
        const float* xr = rT + r2;
#pragma unroll 4
        for (int k = 0; k < ND; k++) {
            float2 xv = *(const float2*)xr;
            float2 wgv = *(const float2*)wg;
            xr += XS; wg += ND;
            ag00 += xv.x * wgv.x; ag01 += xv.x * wgv.y;
            ag10 += xv.y * wgv.x; ag11 += xv.y * wgv.y;
        }
#pragma unroll
        for (int rr = 0; rr < 2; rr++) {
            int r = r2 + rr;
            float m = mrow[r];
            float g0 = fast_tanh(((rr == 0) ? ag00 : ag10) + bg0);
            float g1 = fast_tanh(((rr == 0) ? ag01 : ag11) + bg1);
            float z0 = zT[c2 * XS + r], z1 = zT[(c2 + 1) * XS + r];
            float h0v = h1T[c2 * XS + r], h1v = h1T[(c2 + 1) * XS + r];
            float n0 = (1.f - z0) * h0v + z0 * g0;
            float n1 = (1.f - z1) * h1v + z1 * g1;
            float2 o;
            o.x = h0v + m * (n0 - h0v);
            o.y = h1v + m * (n1 - h1v);
            *(float2*)(post + (v0 + r) * ND + c2) = o;
        }
    }
    if (xp) {
        const int cx = (t & 15) * 2;
        const int r = t >> 4;
        float a0 = 0.f, a1 = 0.f;
        const float* wo = sm + G_WO + cx;
        const float* hq = h1T + r;
#pragma unroll 4
        for (int k = 0; k < ND; k++) {
            float hv = *hq;
            float2 w = *(const float2*)wo;
            hq += XS; wo += NI;
            a0 += hv * w.x; a1 += hv * w.y;
        }
        float2 o;
        o.x = a0 + __ldg(bo + cx);
        o.y = a1 + __ldg(bo + cx + 1);
        *(float2*)(xp + (v0 + r) * NI + cx) = o;
    }
}

__global__ void init_kernel(float* __restrict__ trj) {
    int i = threadIdx.x;
    if (i < 197) trj[i] = 0.25f * (float)i;
}

__global__ void __launch_bounds__(NTHR, 1) __cluster_dims__(CLUSTER, 1, 1)
node_persist(
    const float* __restrict__ values, const float* __restrict__ masks,
    const float* __restrict__ adj, const float* __restrict__ h0,
    const float* __restrict__ Wo_g, const float* __restrict__ bo,
    const float* __restrict__ Win_g, const float* __restrict__ bin,
    const float* __restrict__ Wh_g, const float* __restrict__ bh,
    const float* __restrict__ Wode_g, const float* __restrict__ bode,
    const float* __restrict__ Wr_g, const float* __restrict__ br,
    const float* __restrict__ Wz_g, const float* __restrict__ bz,
    const float* __restrict__ Wg_g, const float* __restrict__ bg,
    float* __restrict__ XP, float* __restrict__ PRE,
    float* __restrict__ PREN, float* __restrict__ POST) {
    extern __shared__ __align__(16) float sm[];
    const int t = threadIdx.x;
    const int b = blockIdx.x >> 4;
    const int v0 = (blockIdx.x & 15) * ROWS;
    const float* adjb = adj + ((long long)b * NV + v0) * NV;
    const long long SL = (long long)NV * ND;
    float* PREb = PRE + (long long)b * 197 * SL;
    float* PRENb = PREN + (long long)b * NT * SL;
    float* POSTb = POST + (long long)b * NT * SL;
    float* XPb = XP + (long long)b * 49 * NV * NI;
    const float* valb = values + (long long)b * NT * NV * NI;
    const float* mskb = masks + (long long)b * NT * NV * NI;

    smcopy(sm + W_IN, Win_g, 8192, t);
    smcopy(sm + W_H0, Wh_g, 16384, t);
    smcopy(sm + W_H1, Wh_g + 16384, 16384, t);
    smcopy(sm + W_OUT, Wode_g, 8192, t);
    __syncthreads();

    euler_step(sm, t, adjb, h0, 1, v0, bin, bh, bh + NH, bode, PREb, PRENb);
    cluster_barrier();

    for (int tt = 0; tt < NT; tt++) {
        smcopy(sm + G_WR, Wr_g, 6144, t);
        smcopy(sm + G_WZ, Wz_g, 6144, t);
        smcopy(sm + G_WG, Wg_g, 6144, t);
        smcopy(sm + G_WO, Wo_g, 2048, t);
        __syncthreads();
        gru_step(sm, t, adjb, PRENb + (long long)tt * SL, v0,
                 valb + (long long)tt * NV * NI, mskb + (long long)tt * NV * NI,
                 br, bz, bg, bo, POSTb + (long long)tt * SL,
                 tt ? (XPb + (long long)(tt - 1) * NV * NI) : nullptr);
        cluster_barrier();
        if (tt < NT - 1) {
            smcopy(sm + W_H0, Wh_g, 16384, t);
            smcopy(sm + W_H1, Wh_g + 16384, 16384, t);
            __syncthreads();
            const float* hin = POSTb + (long long)tt * SL;
#pragma unroll 1
            for (int k = 0; k < 4; k++) {
                float* o1 = PREb + (long long)(1 + 4 * tt + k) * SL;
                float* o2 = (k == 3) ? (PRENb + (long long)(tt + 1) * SL) : nullptr;
                euler_step(sm, t, adjb, hin, 0, v0, bin, bh, bh + NH, bode, o1, o2);
                cluster_barrier();
                hin = o1;
            }
        }
    }
}

extern "C" void kernel_launch(void* const* d_in, const int* in_sizes, int n_in,
                              void* d_out, int out_size) {
    const float* values = (const float*)d_in[0];
    const float* masks  = (const float*)d_in[1];
    const float* adj    = (const float*)d_in[2];
    const float* h0     = (const float*)d_in[3];
    const float* W_out  = (const float*)d_in[4];
    const float* b_out  = (const float*)d_in[5];
    const float* Win    = (const float*)d_in[6];
    const float* bin    = (const float*)d_in[7];
    const float* Wh     = (const float*)d_in[8];
    const float* bh     = (const float*)d_in[9];
    const float* Wode   = (const float*)d_in[10];
    const float* bode   = (const float*)d_in[11];
    const float* Wr     = (const float*)d_in[12];
    const float* br     = (const float*)d_in[13];
    const float* Wz     = (const float*)d_in[14];
    const float* bz     = (const float*)d_in[15];
    const float* Wg     = (const float*)d_in[16];
    const float* bg     = (const float*)d_in[17];

    float* out = (float*)d_out;
    float* XP   = out;
    float* PRE  = XP + (long long)NB * 49 * NV * NI;
    float* PREN = PRE + (long long)NB * 197 * NV * ND;
    float* POST = PREN + (long long)NB * NT * NV * ND;
    float* TRJ  = POST + (long long)NB * NT * NV * ND;

    const size_t smbytes = SM_FLOATS * sizeof(float);
    static int configured = 0;
    if (!configured) {
        cudaFuncSetAttribute(node_persist,
                             cudaFuncAttributeNonPortableClusterSizeAllowed, 1);
        cudaFuncSetAttribute(node_persist,
                             cudaFuncAttributeMaxDynamicSharedMemorySize, (int)smbytes);
        configured = 1;
    }

    init_kernel<<<1, 256>>>(TRJ);
    node_persist<<<GRID, NTHR, smbytes>>>(values, masks, adj, h0, W_out, b_out,
                                          Win, bin, Wh, bh, Wode, bode,
                                          Wr, br, Wz, bz, Wg, bg,
                                          XP, PRE, PREN, POST);
}